// round 2
// baseline (speedup 1.0000x reference)
#include <cuda_runtime.h>
#include <cuda_bf16.h>
#include <math.h>

// Problem constants
#define BB 2
#define LL 1024
#define DD 768
#define HH 12
#define NS 256
#define WW 8
#define TK 50
#define NT 66
#define NR 57
#define NN 20
#define NPAIR ((TK*(TK-1))/2)   // 1225
#define NC (NR+NN)              // 77
#define NE (2*NR+2*NN)          // 154

// Output layout (flattened f32 concat of the reference tuple, guarded by out_size)
#define SZ_SCORES (BB*TK*TK*58)   // 290000
#define SZ_PREDS  (BB*TK*TK)      // 5000
#define SZ_PM     (BB*TK*TK)      // 5000
#define SZ_TOP    (BB*TK)         // 100

// Scratch (static device arrays; no allocations)
__device__ float g_embs[BB*NS*DD];
__device__ float g_spanmax[BB*NS];
__device__ int   g_cls[BB*NS];
__device__ int   g_top[BB*TK];
__device__ int   g_trig[BB*TK];
__device__ float g_eterm[BB*TK*NE];
__device__ float g_swm[BB*LL*NC];
__device__ float g_ae[BB*TK*HH*LL];
__device__ float g_aw[BB*NPAIR*LL];
__device__ float g_gg[BB*NPAIR*NC];
__device__ float g_WT[DD*(NT+NE+NC)];   // anchorT | [W1|W2|M1|M2]T | [W3|M3]T
__device__ float g_redw[BB*TK*8];
__device__ float g_redt[BB*TK];
__device__ int   g_btmode;              // 0=uint8 bool, 1=int32, 2=float32

// ---------------------------------------------------------------------------
// Probe the dtype of the is_trigger buffer from its first 66 bytes.
// uint8 bool: random 0/1 bytes -> some '1' at i%4!=0 (prob miss ~2^-49)
// int32 0/1 : bytes [v,0,0,0]* -> all bytes in {0,1}, 1s only at i%4==0
// float32   : 1.0f = [00,00,80,3F] -> bytes >1 present
// ---------------------------------------------------------------------------
__global__ void k_probe(const unsigned char* __restrict__ p) {
    if (threadIdx.x == 0 && blockIdx.x == 0) {
        int mode = 1;
        bool nonbin = false, oddone = false;
        for (int i = 0; i < 66; ++i) {
            unsigned char v = p[i];
            if (v > 1) nonbin = true;
            else if (v == 1 && (i & 3) != 0) oddone = true;
        }
        if (nonbin) mode = 2;
        else if (oddone) mode = 0;
        g_btmode = mode;
    }
}

// ---------------------------------------------------------------------------
// Prep: transpose small weight matrices for coalesced column access.
// ---------------------------------------------------------------------------
__global__ void k_prep(const float* __restrict__ anchor,
                       const float* __restrict__ rel,
                       const float* __restrict__ nota) {
    int i = blockIdx.x * blockDim.x + threadIdx.x;
    const int totA = DD*NT, totB = DD*NE, totC = DD*NC;
    if (i < totA) {
        int d = i / NT, t = i % NT;
        g_WT[i] = anchor[t*DD + d];
    } else if (i < totA + totB) {
        int i2 = i - totA;
        int d = i2 / NE, j = i2 % NE;
        float v;
        if (j < NR)            v = rel[(size_t)j*3*DD + d];                 // W1
        else if (j < 2*NR)     v = rel[(size_t)(j-NR)*3*DD + DD + d];       // W2
        else if (j < 2*NR+NN)  v = nota[(size_t)(j-2*NR)*3*DD + d];         // M1
        else                   v = nota[(size_t)(j-2*NR-NN)*3*DD + DD + d]; // M2
        g_WT[i] = v;
    } else if (i < totA + totB + totC) {
        int i3 = i - totA - totB;
        int d = i3 / NC, j = i3 % NC;
        float v = (j < NR) ? rel[(size_t)j*3*DD + 2*DD + d]
                           : nota[(size_t)(j-NR)*3*DD + 2*DD + d];
        g_WT[i] = v;
    }
}

// ---------------------------------------------------------------------------
// Span embeddings: embs[b,n,d] = mean over valid window tokens
// ---------------------------------------------------------------------------
__global__ void k_embs(const float* __restrict__ seq,
                       const int* __restrict__ starts,
                       const int* __restrict__ lens) {
    int n = blockIdx.x, b = blockIdx.y;
    int st = starts[b*NS+n];
    int le = lens[b*NS+n];          // valid w: 0..le  (le in [0,7])
    float wt = 1.0f / (float)(le + 1);
    const float* sb = seq + (size_t)b*LL*DD;
    float* eb = g_embs + ((size_t)b*NS + n)*DD;
    for (int d = threadIdx.x; d < DD; d += blockDim.x) {
        float acc = 0.f;
        for (int w = 0; w <= le; ++w) {
            int p = st + w; if (p > LL-1) p = LL-1;
            acc += sb[(size_t)p*DD + d];
        }
        eb[d] = acc * wt;
    }
}

// ---------------------------------------------------------------------------
// Span scores vs entity anchors: per-(b,n) max + argmax over NT=66
// ---------------------------------------------------------------------------
__global__ void k_score() {
    __shared__ float se[DD];
    __shared__ float sv[NT];
    int n = blockIdx.x, b = blockIdx.y;
    const float* eb = g_embs + ((size_t)b*NS + n)*DD;
    for (int d = threadIdx.x; d < DD; d += blockDim.x) se[d] = eb[d];
    __syncthreads();
    int j = threadIdx.x;
    if (j < NT) {
        const float* at = g_WT;   // anchorT: [d*NT + t]
        float acc = 0.f;
        for (int d = 0; d < DD; ++d) acc += se[d] * at[d*NT + j];
        sv[j] = acc;
    }
    __syncthreads();
    if (threadIdx.x == 0) {
        float mx = sv[0]; int mi = 0;
        for (int t = 1; t < NT; ++t) if (sv[t] > mx) { mx = sv[t]; mi = t; }
        g_spanmax[b*NS+n] = mx;
        g_cls[b*NS+n] = mi;
    }
}

// ---------------------------------------------------------------------------
// Top-K per batch (descending, ties -> lower index, matching lax.top_k)
// ---------------------------------------------------------------------------
__global__ void k_topk(const void* __restrict__ istrig,
                       float* __restrict__ out, int write_top) {
    __shared__ float v[NS];
    __shared__ float rv[NS];
    __shared__ int   ri[NS];
    int b = blockIdx.x, t = threadIdx.x;
    v[t] = g_spanmax[b*NS + t];
    __syncthreads();
    for (int k = 0; k < TK; ++k) {
        rv[t] = v[t]; ri[t] = t;
        __syncthreads();
        for (int s = NS/2; s > 0; s >>= 1) {
            if (t < s) {
                float ov = rv[t+s]; int oi = ri[t+s];
                if (ov > rv[t] || (ov == rv[t] && oi < ri[t])) { rv[t] = ov; ri[t] = oi; }
            }
            __syncthreads();
        }
        if (t == 0) {
            int idx = ri[0];
            g_top[b*TK + k] = idx;
            int c = g_cls[b*NS + idx];
            int tv;
            if (g_btmode == 0)      tv = ((const unsigned char*)istrig)[c] != 0;
            else if (g_btmode == 1) tv = ((const int*)istrig)[c] != 0;
            else                    tv = ((const float*)istrig)[c] != 0.0f;
            g_trig[b*TK + k] = tv;
            if (write_top)
                out[SZ_SCORES + SZ_PREDS + SZ_PM + b*TK + k] = (float)idx;
            v[idx] = -INFINITY;
        }
        __syncthreads();
    }
}

// ---------------------------------------------------------------------------
// e-terms: e·W1, e·W2, e·M1, e·M2 for the top-K spans
// ---------------------------------------------------------------------------
__global__ void k_eterm() {
    __shared__ float se[DD];
    int s = blockIdx.x, b = blockIdx.y;
    int n = g_top[b*TK + s];
    const float* eb = g_embs + ((size_t)b*NS + n)*DD;
    for (int d = threadIdx.x; d < DD; d += blockDim.x) se[d] = eb[d];
    __syncthreads();
    int j = threadIdx.x;
    if (j < NE) {
        const float* wt = g_WT + DD*NT;   // W12T: [d*NE + j]
        float acc = 0.f;
        for (int d = 0; d < DD; ++d) acc += se[d] * wt[d*NE + j];
        g_eterm[((size_t)b*TK + s)*NE + j] = acc;
    }
}

// ---------------------------------------------------------------------------
// SWM[b,l,j] = seq[b,l,:] · [W3|M3]T[:,j]   (c-elimination projection)
// ---------------------------------------------------------------------------
__global__ void k_swm(const float* __restrict__ seq) {
    __shared__ float ss[8*DD];    // 24 KB
    int l0 = blockIdx.x * 8, b = blockIdx.y;
    const float* sb = seq + ((size_t)b*LL + l0)*DD;
    for (int i = threadIdx.x; i < 8*DD; i += blockDim.x) ss[i] = sb[i];
    __syncthreads();
    int tid = threadIdx.x;
    if (tid < 8*NC) {
        int j = tid % NC, p = tid / NC;
        const float* wt = g_WT + DD*(NT+NE);   // WM3T: [d*NC + j]
        const float* row = ss + p*DD;
        float acc = 0.f;
        for (int d = 0; d < DD; ++d) acc += row[d] * wt[d*NC + j];
        g_swm[((size_t)b*LL + l0 + p)*NC + j] = acc;
    }
}

// ---------------------------------------------------------------------------
// a_e: attention pooling ONLY for the top-K spans
// ---------------------------------------------------------------------------
__global__ void k_ae(const float* __restrict__ att,
                     const int* __restrict__ starts,
                     const int* __restrict__ lens) {
    int h = blockIdx.x, s = blockIdx.y, b = blockIdx.z;
    int n = g_top[b*TK + s];
    int st = starts[b*NS + n], le = lens[b*NS + n];
    float wt = 1.0f / (float)(le + 1);
    const float* ab = att + ((size_t)(b*HH + h))*LL*LL;
    float* ob = g_ae + (((size_t)b*TK + s)*HH + h)*LL;
    int pos[WW];
#pragma unroll
    for (int w = 0; w < WW; ++w) { int p = st + w; pos[w] = (p > LL-1) ? LL-1 : p; }
    for (int l = threadIdx.x; l < LL; l += blockDim.x) {
        float acc = 0.f;
        for (int w = 0; w <= le; ++w) acc += ab[(size_t)pos[w]*LL + l];
        ob[l] = acc * wt;
    }
}

// ---------------------------------------------------------------------------
// q + aw for upper-triangle pairs only (q symmetric in s,o)
// ---------------------------------------------------------------------------
__global__ void k_qaw() {
    extern __shared__ float sA[];             // HH*LL = 48 KB
    int s = blockIdx.x, b = blockIdx.y;
    const float* aes = g_ae + ((size_t)b*TK + s)*HH*LL;
    for (int i = threadIdx.x; i < HH*LL; i += blockDim.x) sA[i] = aes[i];
    __syncthreads();
    int tid = threadIdx.x;
    int lane = tid & 31, wid = tid >> 5;
    int blk = b*TK + s;
    for (int o = s+1; o < TK; ++o) {
        const float* aeo = g_ae + ((size_t)b*TK + o)*HH*LL;
        float q[4];
        float loc = 0.f;
#pragma unroll
        for (int i = 0; i < 4; ++i) {
            int l = tid + i*256;
            float acc = 0.f;
#pragma unroll
            for (int h = 0; h < HH; ++h) acc += sA[h*LL + l] * aeo[h*LL + l];
            q[i] = acc; loc += acc;
        }
        for (int off = 16; off; off >>= 1) loc += __shfl_down_sync(0xffffffffu, loc, off);
        if (lane == 0) g_redw[blk*8 + wid] = loc;
        __syncthreads();
        if (tid == 0) {
            float tot = 0.f;
            for (int wv = 0; wv < 8; ++wv) tot += g_redw[blk*8 + wv];
            g_redt[blk] = 1.0f / tot;
        }
        __syncthreads();
        float inv = g_redt[blk];
        int pair = s*TK - (s*(s+1))/2 + (o - s - 1);
        float* awp = g_aw + ((size_t)b*NPAIR + pair)*LL;
#pragma unroll
        for (int i = 0; i < 4; ++i) awp[tid + i*256] = q[i] * inv;
        __syncthreads();
    }
}

// ---------------------------------------------------------------------------
// gg[b,pair,j] = sum_l aw[b,pair,l] * SWM[b,l,j]
// ---------------------------------------------------------------------------
__global__ void k_gg() {
    __shared__ float saw[8*LL];   // 32 KB
    int b = blockIdx.y;
    int p0 = blockIdx.x * 8;
    int tid = threadIdx.x;
    int nrows = NPAIR - p0; if (nrows > 8) nrows = 8;
    for (int i = tid; i < nrows*LL; i += blockDim.x)
        saw[i] = g_aw[((size_t)b*NPAIR + p0)*LL + i];
    __syncthreads();
    if (tid < 8*NC) {
        int j = tid % NC, p = tid / NC;
        if (p < nrows) {
            const float* sw = g_swm + (size_t)b*LL*NC + j;
            const float* row = saw + p*LL;
            float acc = 0.f;
            for (int l = 0; l < LL; ++l) acc += row[l] * sw[(size_t)l*NC];
            g_gg[((size_t)b*NPAIR + p0 + p)*NC + j] = acc;
        }
    }
}

// ---------------------------------------------------------------------------
// Final scoring
// ---------------------------------------------------------------------------
__global__ void k_final(float* __restrict__ out, int write_extra) {
    __shared__ float sc[58];
    __shared__ float nv[NN];
    int o = blockIdx.x, s = blockIdx.y, b = blockIdx.z;
    int tid = threadIdx.x;
    int trig = g_trig[b*TK + s];
    int mask = (trig && (s != o)) ? 1 : 0;
    size_t so = ((size_t)b*TK + s)*TK + o;
    float* outs = out + so*58;
    if (!mask) {
        if (tid < 58) outs[tid] = 0.f;
        if (tid == 0 && write_extra) {
            out[SZ_SCORES + so] = 0.f;
            out[SZ_SCORES + SZ_PREDS + so] = 0.f;
        }
        return;
    }
    int lo = s < o ? s : o, hi = s < o ? o : s;
    int pair = lo*TK - (lo*(lo+1))/2 + (hi - lo - 1);
    const float* gg = g_gg + ((size_t)b*NPAIR + pair)*NC;
    const float* es = g_eterm + ((size_t)b*TK + s)*NE;
    const float* eo = g_eterm + ((size_t)b*TK + o)*NE;
    if (tid < NR) sc[1 + tid] = es[tid] + eo[NR + tid] + gg[tid];
    if (tid < NN) nv[tid] = es[2*NR + tid] + eo[2*NR + NN + tid] + gg[NR + tid];
    __syncthreads();
    if (tid == 0) {
        float nm = nv[0];
        for (int m = 1; m < NN; ++m) nm = fmaxf(nm, nv[m]);
        sc[0] = nm;
    }
    __syncthreads();
    if (tid < 58) outs[tid] = sc[tid];
    if (tid == 0) {
        float mx = sc[0]; int mi = 0;
        for (int c = 1; c < 58; ++c) if (sc[c] > mx) { mx = sc[c]; mi = c; }
        if (write_extra) {
            out[SZ_SCORES + so] = (float)mi;
            out[SZ_SCORES + SZ_PREDS + so] = 1.0f;
        }
    }
}

// ---------------------------------------------------------------------------
extern "C" void kernel_launch(void* const* d_in, const int* in_sizes, int n_in,
                              void* d_out, int out_size) {
    const float* seq    = (const float*)d_in[0];  // (B,L,D)
    const float* att    = (const float*)d_in[1];  // (B,H,L,L)
    const float* anchor = (const float*)d_in[2];  // (NT,D)
    const float* rel    = (const float*)d_in[3];  // (NR,3D)
    const float* nota   = (const float*)d_in[4];  // (NN,3D)
    const int* starts   = (const int*)d_in[5];    // (B,N)
    const int* lens     = (const int*)d_in[6];    // (B,N)
    const void* istrig  = d_in[7];                // (NT,) dtype probed on device
    float* out = (float*)d_out;

    // Auxiliary outputs only if the buffer is big enough (avoid OOB under any layout)
    int write_extra = (out_size >= SZ_SCORES + SZ_PREDS + SZ_PM) ? 1 : 0;
    int write_top   = (out_size >= SZ_SCORES + SZ_PREDS + SZ_PM + SZ_TOP) ? 1 : 0;

    k_probe<<<1, 32>>>((const unsigned char*)istrig);
    {
        int total = DD*(NT+NE+NC);
        k_prep<<<(total + 255)/256, 256>>>(anchor, rel, nota);
    }
    k_embs<<<dim3(NS, BB), 256>>>(seq, starts, lens);
    k_score<<<dim3(NS, BB), 128>>>();
    k_topk<<<BB, NS>>>(istrig, out, write_top);
    k_eterm<<<dim3(TK, BB), 192>>>();
    k_swm<<<dim3(LL/8, BB), 640>>>(seq);
    k_ae<<<dim3(HH, TK, BB), 256>>>(att, starts, lens);
    k_qaw<<<dim3(TK, BB), 256, HH*LL*sizeof(float)>>>();
    k_gg<<<dim3((NPAIR + 7)/8, BB), 640>>>();
    k_final<<<dim3(TK, TK, BB), 64>>>(out, write_extra);
}

// round 3
// speedup vs baseline: 2.4146x; 2.4146x over previous
#include <cuda_runtime.h>
#include <cuda_bf16.h>
#include <math.h>

// Problem constants
#define BB 2
#define LL 1024
#define DD 768
#define HH 12
#define NS 256
#define WW 8
#define TK 50
#define NT 66
#define NR 57
#define NN 20
#define NPAIR ((TK*(TK-1))/2)   // 1225
#define NC (NR+NN)              // 77
#define NE (2*NR+2*NN)          // 154

// Output layout (flattened f32 concat, guarded by out_size)
#define SZ_SCORES (BB*TK*TK*58)   // 290000
#define SZ_PREDS  (BB*TK*TK)      // 5000
#define SZ_PM     (BB*TK*TK)      // 5000
#define SZ_TOP    (BB*TK)         // 100

// Scratch (static device arrays)
__device__ float g_embs[BB*NS*DD];
__device__ float g_sps[BB*NS*NT];       // span scores (atomically accumulated)
__device__ int   g_top[BB*TK];
__device__ int   g_trig[BB*TK];
__device__ float g_eterm[BB*TK*NE];
__device__ float g_swm[BB*LL*NC];
__device__ float g_ae[BB*TK*HH*LL];
__device__ float g_q[BB*NPAIR*LL];      // unnormalized q
__device__ float g_qsum[BB*NPAIR];      // per-pair row sums
__device__ float g_gg[BB*NPAIR*NC];
__device__ float g_WT[DD*(NT+NE+NC)];   // anchorT | [W1|W2|M1|M2]T | [W3|M3]T
__device__ int   g_btmode;              // 0=uint8 bool, 1=int32, 2=float32

// ---------------------------------------------------------------------------
// Prep (+ dtype probe for is_trigger buffer)
// ---------------------------------------------------------------------------
__global__ void k_prep(const float* __restrict__ anchor,
                       const float* __restrict__ rel,
                       const float* __restrict__ nota,
                       const unsigned char* __restrict__ bt) {
    int i = blockIdx.x * blockDim.x + threadIdx.x;
    if (i == 0) {
        int mode = 1;
        bool nonbin = false, oddone = false;
        for (int t = 0; t < NT; ++t) {
            unsigned char v = bt[t];
            if (v > 1) nonbin = true;
            else if (v == 1 && (t & 3) != 0) oddone = true;
        }
        if (nonbin) mode = 2;
        else if (oddone) mode = 0;
        g_btmode = mode;
    }
    const int totA = DD*NT, totB = DD*NE, totC = DD*NC;
    if (i < totA) {
        int d = i / NT, t = i % NT;
        g_WT[i] = anchor[t*DD + d];
    } else if (i < totA + totB) {
        int i2 = i - totA;
        int d = i2 / NE, j = i2 % NE;
        float v;
        if (j < NR)            v = rel[(size_t)j*3*DD + d];
        else if (j < 2*NR)     v = rel[(size_t)(j-NR)*3*DD + DD + d];
        else if (j < 2*NR+NN)  v = nota[(size_t)(j-2*NR)*3*DD + d];
        else                   v = nota[(size_t)(j-2*NR-NN)*3*DD + DD + d];
        g_WT[i] = v;
    } else if (i < totA + totB + totC) {
        int i3 = i - totA - totB;
        int d = i3 / NC, j = i3 % NC;
        float v = (j < NR) ? rel[(size_t)j*3*DD + 2*DD + d]
                           : nota[(size_t)(j-NR)*3*DD + 2*DD + d];
        g_WT[i] = v;
    }
}

// ---------------------------------------------------------------------------
// Span embeddings
// ---------------------------------------------------------------------------
__global__ void k_embs(const float* __restrict__ seq,
                       const int* __restrict__ starts,
                       const int* __restrict__ lens) {
    int n = blockIdx.x, b = blockIdx.y;
    int st = starts[b*NS+n];
    int le = lens[b*NS+n];
    float wt = 1.0f / (float)(le + 1);
    const float* sb = seq + (size_t)b*LL*DD;
    float* eb = g_embs + ((size_t)b*NS + n)*DD;
    for (int d = threadIdx.x; d < DD; d += blockDim.x) {
        float acc = 0.f;
        for (int w = 0; w <= le; ++w) {
            int p = st + w; if (p > LL-1) p = LL-1;
            acc += sb[(size_t)p*DD + d];
        }
        eb[d] = acc * wt;
    }
}

// ---------------------------------------------------------------------------
// Generic register-tiled GEMM with k-split: C[b][R][j] (+)= A[b][row(R)][:]·W[b][:][j]
//   TM=64 rows/block, thread tile = 8 rows x MMAX cols (CT=32 col threads)
//   grid.z = k-split; epilogue atomicAdd (C pre-zeroed); optional row scale 1/qsum
// ---------------------------------------------------------------------------
template<int MMAX>
__global__ void k_gemm(const float* __restrict__ A, long sAb,
                       const int* __restrict__ gidx, int gsb,
                       const float* __restrict__ W, long sWb,
                       float* __restrict__ C, long sCb,
                       int M, int N, int K,
                       const float* __restrict__ qsum, int qsb) {
    constexpr int TM = 64;
    constexpr int CT = 32;
    constexpr int NPAD = MMAX*CT;
    __shared__ float As[TM*32];
    __shared__ float Ws[32*NPAD];
    int b = blockIdx.y;
    int r0 = blockIdx.x * TM;
    int tid = threadIdx.x;
    const float* Ab = A + (long)b*sAb;
    const float* Wb = W + (long)b*sWb;
    int kchunk = K / gridDim.z;
    int kbase = blockIdx.z * kchunk;

    float acc[8][MMAX];
#pragma unroll
    for (int i = 0; i < 8; ++i)
#pragma unroll
        for (int m = 0; m < MMAX; ++m) acc[i][m] = 0.f;

    int rg = tid >> 5, ct = tid & 31;

    for (int k0 = kbase; k0 < kbase + kchunk; k0 += 32) {
        for (int e = tid; e < TM*32; e += 256) {
            int r = e >> 5, c = e & 31;
            int R = r0 + r; if (R >= M) R = M-1;
            int row = gidx ? gidx[b*gsb + R] : R;
            As[e] = Ab[(long)row*K + k0 + c];
        }
        for (int e = tid; e < 32*NPAD; e += 256) {
            int r = e / NPAD, c = e % NPAD;
            Ws[e] = (c < N) ? Wb[(long)(k0+r)*N + c] : 0.f;
        }
        __syncthreads();
#pragma unroll 8
        for (int kk = 0; kk < 32; ++kk) {
            float wv[MMAX];
#pragma unroll
            for (int m = 0; m < MMAX; ++m) wv[m] = Ws[kk*NPAD + ct + m*CT];
#pragma unroll
            for (int i = 0; i < 8; ++i) {
                float av = As[(rg*8+i)*32 + kk];
#pragma unroll
                for (int m = 0; m < MMAX; ++m) acc[i][m] += av * wv[m];
            }
        }
        __syncthreads();
    }

#pragma unroll
    for (int i = 0; i < 8; ++i) {
        int R = r0 + rg*8 + i;
        if (R < M) {
            float sc = 1.f;
            if (qsum) sc = 1.f / qsum[b*qsb + R];
#pragma unroll
            for (int m = 0; m < MMAX; ++m) {
                int j = ct + m*CT;
                if (j < N) atomicAdd(&C[(long)b*sCb + (long)R*N + j], acc[i][m]*sc);
            }
        }
    }
}

// ---------------------------------------------------------------------------
// Top-K via stable ranking (descending, ties -> lower index)
// ---------------------------------------------------------------------------
__global__ void k_topk(const void* __restrict__ istrig,
                       float* __restrict__ out, int write_top) {
    __shared__ float sv[NS];
    __shared__ int   sci[NS];
    int b = blockIdx.x, t = threadIdx.x;
    const float* row = g_sps + ((size_t)b*NS + t)*NT;
    float mx = row[0]; int mi = 0;
#pragma unroll
    for (int j = 1; j < NT; ++j) {
        float v = row[j];
        if (v > mx) { mx = v; mi = j; }
    }
    sv[t] = mx; sci[t] = mi;
    __syncthreads();
    int rank = 0;
    float my = sv[t];
    for (int j = 0; j < NS; ++j) {
        float vj = sv[j];
        rank += (vj > my) || (vj == my && j < t);
    }
    if (rank < TK) {
        g_top[b*TK + rank] = t;
        int c = sci[t];
        int tv;
        if (g_btmode == 0)      tv = ((const unsigned char*)istrig)[c] != 0;
        else if (g_btmode == 1) tv = ((const int*)istrig)[c] != 0;
        else                    tv = ((const float*)istrig)[c] != 0.0f;
        g_trig[b*TK + rank] = tv;
        if (write_top)
            out[SZ_SCORES + SZ_PREDS + SZ_PM + b*TK + rank] = (float)t;
    }
}

// ---------------------------------------------------------------------------
// a_e: attention pooling for top-K spans only
// ---------------------------------------------------------------------------
__global__ void k_ae(const float* __restrict__ att,
                     const int* __restrict__ starts,
                     const int* __restrict__ lens) {
    int h = blockIdx.x, s = blockIdx.y, b = blockIdx.z;
    int n = g_top[b*TK + s];
    int st = starts[b*NS + n], le = lens[b*NS + n];
    float wt = 1.0f / (float)(le + 1);
    const float* ab = att + ((size_t)(b*HH + h))*LL*LL;
    float* ob = g_ae + (((size_t)b*TK + s)*HH + h)*LL;
    int pos[WW];
#pragma unroll
    for (int w = 0; w < WW; ++w) { int p = st + w; pos[w] = (p > LL-1) ? LL-1 : p; }
    for (int l = threadIdx.x; l < LL; l += blockDim.x) {
        float acc = 0.f;
        for (int w = 0; w <= le; ++w) acc += ab[(size_t)pos[w]*LL + l];
        ob[l] = acc * wt;
    }
}

// ---------------------------------------------------------------------------
// q kernel: 2D pair tiles. 4 s-slabs in smem (192KB), 16 o streamed in chunks
// of 4 with register tiling. Writes unnormalized q + per-pair sums.
// ---------------------------------------------------------------------------
#define QS 4
#define QO 16
#define QOC 4
#define NST ((TK+QS-1)/QS)   // 13
#define NOT ((TK+QO-1)/QO)   // 4

__device__ __forceinline__ int pair_idx(int s, int o) {
    return s*TK - (s*(s+1))/2 + (o - s - 1);
}

__global__ void k_q() {
    extern __shared__ float4 sA4[];     // QS*HH*LL floats = 192KB
    __shared__ float sred[QS*QOC*8];
    int b = blockIdx.y;
    int st = blockIdx.x % NST, ot = blockIdx.x / NST;
    int s0 = st*QS, o0 = ot*QO;
    {
        int o_hi = o0 + QO - 1; if (o_hi > TK-1) o_hi = TK-1;
        if (o_hi <= s0) return;   // no valid pair in tile
    }
    int tid = threadIdx.x;
    // load 4 s slabs (clamped)
    for (int idx = tid; idx < QS*HH*(LL/4); idx += 256) {
        int si = idx / (HH*(LL/4));
        int rem = idx % (HH*(LL/4));
        int sc = s0 + si; if (sc > TK-1) sc = TK-1;
        sA4[idx] = ((const float4*)(g_ae + ((size_t)(b*TK + sc)*HH)*LL))[rem];
    }
    __syncthreads();
    int lane = tid & 31, wid = tid >> 5;

    for (int oc = 0; oc < QO; oc += QOC) {
        int ob = o0 + oc;
        if (ob + QOC - 1 <= s0) continue;   // uniform skip
        const float4* aeo[QOC];
#pragma unroll
        for (int oo = 0; oo < QOC; ++oo) {
            int o = ob + oo; if (o > TK-1) o = TK-1;
            aeo[oo] = (const float4*)(g_ae + ((size_t)(b*TK + o)*HH)*LL);
        }
        float4 qv[QS][QOC];
#pragma unroll
        for (int si = 0; si < QS; ++si)
#pragma unroll
            for (int oo = 0; oo < QOC; ++oo) qv[si][oo] = make_float4(0,0,0,0);

#pragma unroll
        for (int h = 0; h < HH; ++h) {
            float4 a[QS];
#pragma unroll
            for (int si = 0; si < QS; ++si) a[si] = sA4[(si*HH + h)*(LL/4) + tid];
#pragma unroll
            for (int oo = 0; oo < QOC; ++oo) {
                float4 x = aeo[oo][h*(LL/4) + tid];
#pragma unroll
                for (int si = 0; si < QS; ++si) {
                    qv[si][oo].x += a[si].x * x.x;
                    qv[si][oo].y += a[si].y * x.y;
                    qv[si][oo].z += a[si].z * x.z;
                    qv[si][oo].w += a[si].w * x.w;
                }
            }
        }
        // store + reduce sums
#pragma unroll
        for (int oo = 0; oo < QOC; ++oo) {
            int o = ob + oo;
#pragma unroll
            for (int si = 0; si < QS; ++si) {
                int s = s0 + si;
                float ps = 0.f;
                if (o < TK && s < o) {
                    int pr = pair_idx(s, o);
                    ((float4*)(g_q + ((size_t)b*NPAIR + pr)*LL))[tid] = qv[si][oo];
                    float4 v = qv[si][oo];
                    ps = v.x + v.y + v.z + v.w;
                }
                for (int off = 16; off; off >>= 1)
                    ps += __shfl_down_sync(0xffffffffu, ps, off);
                if (lane == 0) sred[(si*QOC + oo)*8 + wid] = ps;
            }
        }
        __syncthreads();
        if (tid < QS*QOC) {
            int si = tid / QOC, oo = tid % QOC;
            int s = s0 + si, o = ob + oo;
            if (o < TK && s < o) {
                float tot = 0.f;
#pragma unroll
                for (int w = 0; w < 8; ++w) tot += sred[tid*8 + w];
                g_qsum[(size_t)b*NPAIR + pair_idx(s, o)] = tot;
            }
        }
        __syncthreads();
    }
}

// ---------------------------------------------------------------------------
// Final scoring
// ---------------------------------------------------------------------------
__global__ void k_final(float* __restrict__ out, int write_extra) {
    __shared__ float sc[58];
    __shared__ float nv[NN];
    int o = blockIdx.x, s = blockIdx.y, b = blockIdx.z;
    int tid = threadIdx.x;
    int trig = g_trig[b*TK + s];
    int mask = (trig && (s != o)) ? 1 : 0;
    size_t so = ((size_t)b*TK + s)*TK + o;
    float* outs = out + so*58;
    if (!mask) {
        if (tid < 58) outs[tid] = 0.f;
        if (tid == 0 && write_extra) {
            out[SZ_SCORES + so] = 0.f;
            out[SZ_SCORES + SZ_PREDS + so] = 0.f;
        }
        return;
    }
    int lo = s < o ? s : o, hi = s < o ? o : s;
    int pair = lo*TK - (lo*(lo+1))/2 + (hi - lo - 1);
    const float* gg = g_gg + ((size_t)b*NPAIR + pair)*NC;
    const float* es = g_eterm + ((size_t)b*TK + s)*NE;
    const float* eo = g_eterm + ((size_t)b*TK + o)*NE;
    if (tid < NR) sc[1 + tid] = es[tid] + eo[NR + tid] + gg[tid];
    if (tid < NN) nv[tid] = es[2*NR + tid] + eo[2*NR + NN + tid] + gg[NR + tid];
    __syncthreads();
    if (tid == 0) {
        float nm = nv[0];
        for (int m = 1; m < NN; ++m) nm = fmaxf(nm, nv[m]);
        sc[0] = nm;
    }
    __syncthreads();
    if (tid < 58) outs[tid] = sc[tid];
    if (tid == 0) {
        float mx = sc[0]; int mi = 0;
        for (int c = 1; c < 58; ++c) if (sc[c] > mx) { mx = sc[c]; mi = c; }
        if (write_extra) {
            out[SZ_SCORES + so] = (float)mi;
            out[SZ_SCORES + SZ_PREDS + so] = 1.0f;
        }
    }
}

// ---------------------------------------------------------------------------
extern "C" void kernel_launch(void* const* d_in, const int* in_sizes, int n_in,
                              void* d_out, int out_size) {
    const float* seq    = (const float*)d_in[0];
    const float* att    = (const float*)d_in[1];
    const float* anchor = (const float*)d_in[2];
    const float* rel    = (const float*)d_in[3];
    const float* nota   = (const float*)d_in[4];
    const int* starts   = (const int*)d_in[5];
    const int* lens     = (const int*)d_in[6];
    const void* istrig  = d_in[7];
    float* out = (float*)d_out;

    int write_extra = (out_size >= SZ_SCORES + SZ_PREDS + SZ_PM) ? 1 : 0;
    int write_top   = (out_size >= SZ_SCORES + SZ_PREDS + SZ_PM + SZ_TOP) ? 1 : 0;

    // device symbol addresses
    void *p_embs, *p_sps, *p_top, *p_eterm, *p_swm, *p_q, *p_qsum, *p_gg, *p_wt;
    cudaGetSymbolAddress(&p_embs, g_embs);
    cudaGetSymbolAddress(&p_sps, g_sps);
    cudaGetSymbolAddress(&p_top, g_top);
    cudaGetSymbolAddress(&p_eterm, g_eterm);
    cudaGetSymbolAddress(&p_swm, g_swm);
    cudaGetSymbolAddress(&p_q, g_q);
    cudaGetSymbolAddress(&p_qsum, g_qsum);
    cudaGetSymbolAddress(&p_gg, g_gg);
    cudaGetSymbolAddress(&p_wt, g_WT);

    // zero atomically-accumulated outputs
    cudaMemsetAsync(p_sps, 0, sizeof(float)*BB*NS*NT, 0);
    cudaMemsetAsync(p_eterm, 0, sizeof(float)*BB*TK*NE, 0);
    cudaMemsetAsync(p_swm, 0, sizeof(float)*BB*LL*NC, 0);
    cudaMemsetAsync(p_gg, 0, sizeof(float)*BB*NPAIR*NC, 0);

    k_prep<<<(DD*(NT+NE+NC) + 255)/256, 256>>>(anchor, rel, nota,
                                               (const unsigned char*)istrig);
    k_embs<<<dim3(NS, BB), 256>>>(seq, starts, lens);

    // span scores: [256x768]x[768x66] per batch
    k_gemm<3><<<dim3(4, BB, 8), 256>>>(
        (const float*)p_embs, (long)NS*DD, nullptr, 0,
        (const float*)p_wt, 0,
        (float*)p_sps, (long)NS*NT, NS, NT, DD, nullptr, 0);

    k_topk<<<BB, NS>>>(istrig, out, write_top);

    // e-terms: gathered [50x768]x[768x154]
    k_gemm<5><<<dim3(1, BB, 8), 256>>>(
        (const float*)p_embs, (long)NS*DD, (const int*)p_top, TK,
        (const float*)p_wt + DD*NT, 0,
        (float*)p_eterm, (long)TK*NE, TK, NE, DD, nullptr, 0);

    // SWM: [1024x768]x[768x77] per batch
    k_gemm<3><<<dim3(16, BB, 8), 256>>>(
        seq, (long)LL*DD, nullptr, 0,
        (const float*)p_wt + DD*(NT+NE), 0,
        (float*)p_swm, (long)LL*NC, LL, NC, DD, nullptr, 0);

    k_ae<<<dim3(HH, TK, BB), 256>>>(att, starts, lens);

    cudaFuncSetAttribute(k_q, cudaFuncAttributeMaxDynamicSharedMemorySize,
                         QS*HH*LL*(int)sizeof(float));
    k_q<<<dim3(NST*NOT, BB), 256, QS*HH*LL*sizeof(float)>>>();

    // gg: [1225x1024]x[1024x77] per batch, scaled by 1/qsum
    k_gemm<3><<<dim3(20, BB, 8), 256>>>(
        (const float*)p_q, (long)NPAIR*LL, nullptr, 0,
        (const float*)p_swm, (long)LL*NC,
        (float*)p_gg, (long)NPAIR*NC, NPAIR, NC, LL,
        (const float*)p_qsum, NPAIR);

    k_final<<<dim3(TK, TK, BB), 64>>>(out, write_extra);
}

// round 4
// speedup vs baseline: 3.2206x; 1.3338x over previous
#include <cuda_runtime.h>
#include <cuda_bf16.h>
#include <math.h>

// Problem constants
#define BB 2
#define LL 1024
#define DD 768
#define HH 12
#define NS 256
#define WW 8
#define TK 50
#define NT 66
#define NR 57
#define NN 20
#define NPAIR ((TK*(TK-1))/2)   // 1225
#define NC (NR+NN)              // 77
#define NE (2*NR+2*NN)          // 154

// Output layout (flattened f32 concat, guarded by out_size)
#define SZ_SCORES (BB*TK*TK*58)   // 290000
#define SZ_PREDS  (BB*TK*TK)      // 5000
#define SZ_PM     (BB*TK*TK)      // 5000
#define SZ_TOP    (BB*TK)         // 100

// Zero-fill extents (atomically accumulated buffers)
#define ZSPS (BB*NS*NT)       // 33792
#define ZET  (BB*TK*NE)       // 15400
#define ZSWM (BB*LL*NC)       // 157696
#define ZGG  (BB*NPAIR*NC)    // 188650
#define ZTOT (ZSPS+ZET+ZSWM+ZGG)

// Scratch (static device arrays)
__device__ float g_embs[BB*NS*DD];
__device__ float g_sps[BB*NS*NT];       // span scores, TRANSPOSED per batch: [j][n]
__device__ int   g_top[BB*TK];
__device__ int   g_trig[BB*TK];
__device__ float g_eterm[BB*TK*NE];
__device__ float g_swm[BB*LL*NC];
__device__ float g_ae[BB*TK*HH*LL];
__device__ float g_q[BB*NPAIR*LL];      // unnormalized q
__device__ float g_qsum[BB*NPAIR];
__device__ float g_gg[BB*NPAIR*NC];
__device__ float g_WT[DD*(NT+NE+NC)];   // anchorT | [W1|W2|M1|M2]T | [W3|M3]T
__device__ int   g_btmode;              // 0=uint8 bool, 1=int32, 2=float32

// ---------------------------------------------------------------------------
// Prep: weight transposes + zero-fill of atomic accumulators + dtype probe
// ---------------------------------------------------------------------------
__global__ void k_prep(const float* __restrict__ anchor,
                       const float* __restrict__ rel,
                       const float* __restrict__ nota,
                       const unsigned char* __restrict__ bt) {
    int i = blockIdx.x * blockDim.x + threadIdx.x;
    if (i == 0) {
        int mode = 1;
        bool nonbin = false, oddone = false;
        for (int t = 0; t < NT; ++t) {
            unsigned char v = bt[t];
            if (v > 1) nonbin = true;
            else if (v == 1 && (t & 3) != 0) oddone = true;
        }
        if (nonbin) mode = 2;
        else if (oddone) mode = 0;
        g_btmode = mode;
    }
    // zero-fill
    if (i < ZTOT) {
        int z = i;
        if (z < ZSPS) g_sps[z] = 0.f;
        else if ((z -= ZSPS) < ZET) g_eterm[z] = 0.f;
        else if ((z -= ZET) < ZSWM) g_swm[z] = 0.f;
        else g_gg[z - ZSWM] = 0.f;
    }
    // weight transposes
    const int totA = DD*NT, totB = DD*NE, totC = DD*NC;
    if (i < totA) {
        int d = i / NT, t = i % NT;
        g_WT[i] = anchor[t*DD + d];
    } else if (i < totA + totB) {
        int i2 = i - totA;
        int d = i2 / NE, j = i2 % NE;
        float v;
        if (j < NR)            v = rel[(size_t)j*3*DD + d];
        else if (j < 2*NR)     v = rel[(size_t)(j-NR)*3*DD + DD + d];
        else if (j < 2*NR+NN)  v = nota[(size_t)(j-2*NR)*3*DD + d];
        else                   v = nota[(size_t)(j-2*NR-NN)*3*DD + DD + d];
        g_WT[i] = v;
    } else if (i < totA + totB + totC) {
        int i3 = i - totA - totB;
        int d = i3 / NC, j = i3 % NC;
        float v = (j < NR) ? rel[(size_t)j*3*DD + 2*DD + d]
                           : nota[(size_t)(j-NR)*3*DD + 2*DD + d];
        g_WT[i] = v;
    }
}

// ---------------------------------------------------------------------------
// Span embeddings
// ---------------------------------------------------------------------------
__global__ void k_embs(const float* __restrict__ seq,
                       const int* __restrict__ starts,
                       const int* __restrict__ lens) {
    int n = blockIdx.x, b = blockIdx.y;
    int st = starts[b*NS+n];
    int le = lens[b*NS+n];
    float wt = 1.0f / (float)(le + 1);
    const float* sb = seq + (size_t)b*LL*DD;
    float* eb = g_embs + ((size_t)b*NS + n)*DD;
    for (int d = threadIdx.x; d < DD; d += blockDim.x) {
        float acc = 0.f;
        for (int w = 0; w <= le; ++w) {
            int p = st + w; if (p > LL-1) p = LL-1;
            acc += sb[(size_t)p*DD + d];
        }
        eb[d] = acc * wt;
    }
}

// ---------------------------------------------------------------------------
// Register-tiled GEMM with k-split + atomic epilogue (+ optional transposed C,
// optional row gather, optional 1/qsum row scaling)
// ---------------------------------------------------------------------------
template<int MMAX>
__global__ void k_gemm(const float* __restrict__ A, long sAb,
                       const int* __restrict__ gidx, int gsb,
                       const float* __restrict__ W, long sWb,
                       float* __restrict__ C, long sCb,
                       int M, int N, int K,
                       const float* __restrict__ qsum, int qsb,
                       int ctrans) {
    constexpr int TM = 64;
    constexpr int CT = 32;
    constexpr int NPAD = MMAX*CT;
    __shared__ float As[TM*32];
    __shared__ float Ws[32*NPAD];
    int b = blockIdx.y;
    int r0 = blockIdx.x * TM;
    int tid = threadIdx.x;
    const float* Ab = A + (long)b*sAb;
    const float* Wb = W + (long)b*sWb;
    int kchunk = K / gridDim.z;
    int kbase = blockIdx.z * kchunk;

    float acc[8][MMAX];
#pragma unroll
    for (int i = 0; i < 8; ++i)
#pragma unroll
        for (int m = 0; m < MMAX; ++m) acc[i][m] = 0.f;

    int rg = tid >> 5, ct = tid & 31;

    for (int k0 = kbase; k0 < kbase + kchunk; k0 += 32) {
        for (int e = tid; e < TM*32; e += 256) {
            int r = e >> 5, c = e & 31;
            int R = r0 + r; if (R >= M) R = M-1;
            int row = gidx ? gidx[b*gsb + R] : R;
            As[e] = Ab[(long)row*K + k0 + c];
        }
        for (int e = tid; e < 32*NPAD; e += 256) {
            int r = e / NPAD, c = e % NPAD;
            Ws[e] = (c < N) ? Wb[(long)(k0+r)*N + c] : 0.f;
        }
        __syncthreads();
#pragma unroll 8
        for (int kk = 0; kk < 32; ++kk) {
            float wv[MMAX];
#pragma unroll
            for (int m = 0; m < MMAX; ++m) wv[m] = Ws[kk*NPAD + ct + m*CT];
#pragma unroll
            for (int i = 0; i < 8; ++i) {
                float av = As[(rg*8+i)*32 + kk];
#pragma unroll
                for (int m = 0; m < MMAX; ++m) acc[i][m] += av * wv[m];
            }
        }
        __syncthreads();
    }

#pragma unroll
    for (int i = 0; i < 8; ++i) {
        int R = r0 + rg*8 + i;
        if (R < M) {
            float sc = 1.f;
            if (qsum) sc = 1.f / qsum[b*qsb + R];
#pragma unroll
            for (int m = 0; m < MMAX; ++m) {
                int j = ct + m*CT;
                if (j < N) {
                    long idx = ctrans ? ((long)j*M + R) : ((long)R*N + j);
                    atomicAdd(&C[(long)b*sCb + idx], acc[i][m]*sc);
                }
            }
        }
    }
}

// ---------------------------------------------------------------------------
// Top-K via stable ranking; scores are TRANSPOSED [j][n] -> coalesced
// ---------------------------------------------------------------------------
__global__ void k_topk(const void* __restrict__ istrig,
                       float* __restrict__ out, int write_top) {
    __shared__ float sv[NS];
    __shared__ int   sci[NS];
    int b = blockIdx.x, t = threadIdx.x;
    const float* sp = g_sps + (size_t)b*NS*NT;
    float mx = sp[t]; int mi = 0;
#pragma unroll
    for (int j = 1; j < NT; ++j) {
        float v = sp[(size_t)j*NS + t];
        if (v > mx) { mx = v; mi = j; }
    }
    sv[t] = mx; sci[t] = mi;
    __syncthreads();
    int rank = 0;
    float my = sv[t];
#pragma unroll 8
    for (int j = 0; j < NS; ++j) {
        float vj = sv[j];
        rank += (vj > my) || (vj == my && j < t);
    }
    if (rank < TK) {
        g_top[b*TK + rank] = t;
        int c = sci[t];
        int tv;
        if (g_btmode == 0)      tv = ((const unsigned char*)istrig)[c] != 0;
        else if (g_btmode == 1) tv = ((const int*)istrig)[c] != 0;
        else                    tv = ((const float*)istrig)[c] != 0.0f;
        g_trig[b*TK + rank] = tv;
        if (write_top)
            out[SZ_SCORES + SZ_PREDS + SZ_PM + b*TK + rank] = (float)t;
    }
}

// ---------------------------------------------------------------------------
// a_e: attention pooling for top-K spans only
// ---------------------------------------------------------------------------
__global__ void k_ae(const float* __restrict__ att,
                     const int* __restrict__ starts,
                     const int* __restrict__ lens) {
    int h = blockIdx.x, s = blockIdx.y, b = blockIdx.z;
    int n = g_top[b*TK + s];
    int st = starts[b*NS + n], le = lens[b*NS + n];
    float wt = 1.0f / (float)(le + 1);
    const float* ab = att + ((size_t)(b*HH + h))*LL*LL;
    float* ob = g_ae + (((size_t)b*TK + s)*HH + h)*LL;
    int pos[WW];
#pragma unroll
    for (int w = 0; w < WW; ++w) { int p = st + w; pos[w] = (p > LL-1) ? LL-1 : p; }
    for (int l = threadIdx.x; l < LL; l += blockDim.x) {
        float acc = 0.f;
        for (int w = 0; w <= le; ++w) acc += ab[(size_t)pos[w]*LL + l];
        ob[l] = acc * wt;
    }
}

// ---------------------------------------------------------------------------
// q kernel: 2D pair tiles; 4 s-slabs in 192KB smem, o streamed in chunks of 4.
// Writes unnormalized q + per-pair sums (normalization folded into gg GEMM).
// ---------------------------------------------------------------------------
#define QS 4
#define QO 16
#define QOC 4
#define NST ((TK+QS-1)/QS)   // 13
#define NOT ((TK+QO-1)/QO)   // 4

__device__ __forceinline__ int pair_idx(int s, int o) {
    return s*TK - (s*(s+1))/2 + (o - s - 1);
}

__global__ void k_q() {
    extern __shared__ float4 sA4[];     // QS*HH*LL floats = 192KB
    __shared__ float sred[QS*QOC*8];
    int b = blockIdx.y;
    int st = blockIdx.x % NST, ot = blockIdx.x / NST;
    int s0 = st*QS, o0 = ot*QO;
    {
        int o_hi = o0 + QO - 1; if (o_hi > TK-1) o_hi = TK-1;
        if (o_hi <= s0) return;
    }
    int tid = threadIdx.x;
    for (int idx = tid; idx < QS*HH*(LL/4); idx += 256) {
        int si = idx / (HH*(LL/4));
        int rem = idx % (HH*(LL/4));
        int sc = s0 + si; if (sc > TK-1) sc = TK-1;
        sA4[idx] = ((const float4*)(g_ae + ((size_t)(b*TK + sc)*HH)*LL))[rem];
    }
    __syncthreads();
    int lane = tid & 31, wid = tid >> 5;

    for (int oc = 0; oc < QO; oc += QOC) {
        int ob = o0 + oc;
        if (ob + QOC - 1 <= s0) continue;
        const float4* aeo[QOC];
#pragma unroll
        for (int oo = 0; oo < QOC; ++oo) {
            int o = ob + oo; if (o > TK-1) o = TK-1;
            aeo[oo] = (const float4*)(g_ae + ((size_t)(b*TK + o)*HH)*LL);
        }
        float4 qv[QS][QOC];
#pragma unroll
        for (int si = 0; si < QS; ++si)
#pragma unroll
            for (int oo = 0; oo < QOC; ++oo) qv[si][oo] = make_float4(0,0,0,0);

#pragma unroll
        for (int h = 0; h < HH; ++h) {
            float4 a[QS];
#pragma unroll
            for (int si = 0; si < QS; ++si) a[si] = sA4[(si*HH + h)*(LL/4) + tid];
#pragma unroll
            for (int oo = 0; oo < QOC; ++oo) {
                float4 x = aeo[oo][h*(LL/4) + tid];
#pragma unroll
                for (int si = 0; si < QS; ++si) {
                    qv[si][oo].x += a[si].x * x.x;
                    qv[si][oo].y += a[si].y * x.y;
                    qv[si][oo].z += a[si].z * x.z;
                    qv[si][oo].w += a[si].w * x.w;
                }
            }
        }
#pragma unroll
        for (int oo = 0; oo < QOC; ++oo) {
            int o = ob + oo;
#pragma unroll
            for (int si = 0; si < QS; ++si) {
                int s = s0 + si;
                float ps = 0.f;
                if (o < TK && s < o) {
                    int pr = pair_idx(s, o);
                    ((float4*)(g_q + ((size_t)b*NPAIR + pr)*LL))[tid] = qv[si][oo];
                    float4 v = qv[si][oo];
                    ps = v.x + v.y + v.z + v.w;
                }
                for (int off = 16; off; off >>= 1)
                    ps += __shfl_down_sync(0xffffffffu, ps, off);
                if (lane == 0) sred[(si*QOC + oo)*8 + wid] = ps;
            }
        }
        __syncthreads();
        if (tid < QS*QOC) {
            int si = tid / QOC, oo = tid % QOC;
            int s = s0 + si, o = ob + oo;
            if (o < TK && s < o) {
                float tot = 0.f;
#pragma unroll
                for (int w = 0; w < 8; ++w) tot += sred[tid*8 + w];
                g_qsum[(size_t)b*NPAIR + pair_idx(s, o)] = tot;
            }
        }
        __syncthreads();
    }
}

// ---------------------------------------------------------------------------
// Final scoring
// ---------------------------------------------------------------------------
__global__ void k_final(float* __restrict__ out, int write_extra) {
    __shared__ float sc[58];
    __shared__ float nv[NN];
    int o = blockIdx.x, s = blockIdx.y, b = blockIdx.z;
    int tid = threadIdx.x;
    int trig = g_trig[b*TK + s];
    int mask = (trig && (s != o)) ? 1 : 0;
    size_t so = ((size_t)b*TK + s)*TK + o;
    float* outs = out + so*58;
    if (!mask) {
        if (tid < 58) outs[tid] = 0.f;
        if (tid == 0 && write_extra) {
            out[SZ_SCORES + so] = 0.f;
            out[SZ_SCORES + SZ_PREDS + so] = 0.f;
        }
        return;
    }
    int lo = s < o ? s : o, hi = s < o ? o : s;
    int pair = lo*TK - (lo*(lo+1))/2 + (hi - lo - 1);
    const float* gg = g_gg + ((size_t)b*NPAIR + pair)*NC;
    const float* es = g_eterm + ((size_t)b*TK + s)*NE;
    const float* eo = g_eterm + ((size_t)b*TK + o)*NE;
    if (tid < NR) sc[1 + tid] = es[tid] + eo[NR + tid] + gg[tid];
    if (tid < NN) nv[tid] = es[2*NR + tid] + eo[2*NR + NN + tid] + gg[NR + tid];
    __syncthreads();
    if (tid == 0) {
        float nm = nv[0];
        for (int m = 1; m < NN; ++m) nm = fmaxf(nm, nv[m]);
        sc[0] = nm;
    }
    __syncthreads();
    if (tid < 58) outs[tid] = sc[tid];
    if (tid == 0) {
        float mx = sc[0]; int mi = 0;
        for (int c = 1; c < 58; ++c) if (sc[c] > mx) { mx = sc[c]; mi = c; }
        if (write_extra) {
            out[SZ_SCORES + so] = (float)mi;
            out[SZ_SCORES + SZ_PREDS + so] = 1.0f;
        }
    }
}

// ---------------------------------------------------------------------------
extern "C" void kernel_launch(void* const* d_in, const int* in_sizes, int n_in,
                              void* d_out, int out_size) {
    const float* seq    = (const float*)d_in[0];
    const float* att    = (const float*)d_in[1];
    const float* anchor = (const float*)d_in[2];
    const float* rel    = (const float*)d_in[3];
    const float* nota   = (const float*)d_in[4];
    const int* starts   = (const int*)d_in[5];
    const int* lens     = (const int*)d_in[6];
    const void* istrig  = d_in[7];
    float* out = (float*)d_out;

    int write_extra = (out_size >= SZ_SCORES + SZ_PREDS + SZ_PM) ? 1 : 0;
    int write_top   = (out_size >= SZ_SCORES + SZ_PREDS + SZ_PM + SZ_TOP) ? 1 : 0;

    void *p_embs, *p_sps, *p_top, *p_eterm, *p_swm, *p_q, *p_qsum, *p_gg, *p_wt;
    cudaGetSymbolAddress(&p_embs, g_embs);
    cudaGetSymbolAddress(&p_sps, g_sps);
    cudaGetSymbolAddress(&p_top, g_top);
    cudaGetSymbolAddress(&p_eterm, g_eterm);
    cudaGetSymbolAddress(&p_swm, g_swm);
    cudaGetSymbolAddress(&p_q, g_q);
    cudaGetSymbolAddress(&p_qsum, g_qsum);
    cudaGetSymbolAddress(&p_gg, g_gg);
    cudaGetSymbolAddress(&p_wt, g_WT);

    // Lazily created side streams + events (created on first, non-captured call)
    static cudaStream_t s1 = nullptr, s2 = nullptr;
    static cudaEvent_t eF = nullptr, eP = nullptr, eT = nullptr, eE = nullptr, eQ = nullptr;
    static int smem_set = 0;
    if (!s1) {
        cudaStreamCreateWithFlags(&s1, cudaStreamNonBlocking);
        cudaStreamCreateWithFlags(&s2, cudaStreamNonBlocking);
        cudaEventCreateWithFlags(&eF, cudaEventDisableTiming);
        cudaEventCreateWithFlags(&eP, cudaEventDisableTiming);
        cudaEventCreateWithFlags(&eT, cudaEventDisableTiming);
        cudaEventCreateWithFlags(&eE, cudaEventDisableTiming);
        cudaEventCreateWithFlags(&eQ, cudaEventDisableTiming);
    }
    if (!smem_set) {
        cudaFuncSetAttribute(k_q, cudaFuncAttributeMaxDynamicSharedMemorySize,
                             QS*HH*LL*(int)sizeof(float));
        smem_set = 1;
    }

    // Fork side streams from the origin stream
    cudaEventRecord(eF, 0);
    cudaStreamWaitEvent(s1, eF, 0);
    cudaStreamWaitEvent(s2, eF, 0);

    // main: prep (weights + zeroing + probe)
    k_prep<<<(ZTOT + 255)/256, 256>>>(anchor, rel, nota,
                                      (const unsigned char*)istrig);
    cudaEventRecord(eP, 0);

    // s1 chain: embs -> score -> topk -> eterm
    k_embs<<<dim3(NS, BB), 256, 0, s1>>>(seq, starts, lens);
    cudaStreamWaitEvent(s1, eP, 0);
    k_gemm<3><<<dim3(4, BB, 12), 256, 0, s1>>>(
        (const float*)p_embs, (long)NS*DD, nullptr, 0,
        (const float*)p_wt, 0,
        (float*)p_sps, (long)NS*NT, NS, NT, DD, nullptr, 0, 1 /*ctrans*/);
    k_topk<<<BB, NS, 0, s1>>>(istrig, out, write_top);
    cudaEventRecord(eT, s1);
    k_gemm<5><<<dim3(1, BB, 24), 256, 0, s1>>>(
        (const float*)p_embs, (long)NS*DD, (const int*)p_top, TK,
        (const float*)p_wt + DD*NT, 0,
        (float*)p_eterm, (long)TK*NE, TK, NE, DD, nullptr, 0, 0);
    cudaEventRecord(eE, s1);

    // main chain: swm (independent of topk)
    k_gemm<3><<<dim3(16, BB, 8), 256>>>(
        seq, (long)LL*DD, nullptr, 0,
        (const float*)p_wt + DD*(NT+NE), 0,
        (float*)p_swm, (long)LL*NC, LL, NC, DD, nullptr, 0, 0);

    // s2 chain: ae -> q  (needs topk)
    cudaStreamWaitEvent(s2, eT, 0);
    k_ae<<<dim3(HH, TK, BB), 256, 0, s2>>>(att, starts, lens);
    k_q<<<dim3(NST*NOT, BB), 256, QS*HH*LL*sizeof(float), s2>>>();
    cudaEventRecord(eQ, s2);

    // main: gg (needs swm in-stream + q via event), then final (needs eterm)
    cudaStreamWaitEvent(0, eQ, 0);
    k_gemm<3><<<dim3(20, BB, 8), 256>>>(
        (const float*)p_q, (long)NPAIR*LL, nullptr, 0,
        (const float*)p_swm, (long)LL*NC,
        (float*)p_gg, (long)NPAIR*NC, NPAIR, NC, LL,
        (const float*)p_qsum, NPAIR, 0);
    cudaStreamWaitEvent(0, eE, 0);
    k_final<<<dim3(TK, TK, BB), 64>>>(out, write_extra);
}

// round 5
// speedup vs baseline: 3.3715x; 1.0469x over previous
#include <cuda_runtime.h>
#include <cuda_bf16.h>
#include <math.h>

// Problem constants
#define BB 2
#define LL 1024
#define DD 768
#define HH 12
#define NS 256
#define WW 8
#define TK 50
#define NT 66
#define NR 57
#define NN 20
#define NPAIR ((TK*(TK-1))/2)   // 1225
#define NC (NR+NN)              // 77
#define NE (2*NR+2*NN)          // 154

// Output layout (flattened f32 concat, guarded by out_size)
#define SZ_SCORES (BB*TK*TK*58)   // 290000
#define SZ_PREDS  (BB*TK*TK)      // 5000
#define SZ_PM     (BB*TK*TK)      // 5000
#define SZ_TOP    (BB*TK)         // 100

// Zero-fill extents (atomically accumulated buffers)
#define ZSPS (BB*NS*NT)
#define ZET  (BB*TK*NE)
#define ZSWM (BB*LL*NC)
#define ZGG  (BB*NPAIR*NC)
#define ZTOT (ZSPS+ZET+ZSWM+ZGG)
#define PREP_BLOCKS ((ZTOT + 255)/256)

// Scratch (static device arrays)
__device__ float g_embs[BB*NS*DD];
__device__ float g_sps[BB*NS*NT];       // span scores, TRANSPOSED per batch: [j][n]
__device__ int   g_top[BB*TK];
__device__ int   g_trig[BB*TK];
__device__ float g_eterm[BB*TK*NE];
__device__ float g_swm[BB*LL*NC];
__device__ float g_ae[BB*TK*HH*LL];
__device__ float g_q[BB*NPAIR*LL];      // unnormalized q
__device__ float g_qsum[BB*NPAIR];
__device__ float g_gg[BB*NPAIR*NC];
__device__ float g_WT[DD*(NT+NE+NC)];   // anchorT | [W1|W2|M1|M2]T | [W3|M3]T
__device__ int   g_btmode;              // 0=uint8 bool, 1=int32, 2=float32

// ---------------------------------------------------------------------------
// Fused prep + embs:
//   blocks [0, NS*BB): span embeddings (float4)
//   blocks [NS*BB, ...): weight transposes + zero-fill + dtype probe
// ---------------------------------------------------------------------------
__global__ void k_prep_embs(const float* __restrict__ seq,
                            const int* __restrict__ starts,
                            const int* __restrict__ lens,
                            const float* __restrict__ anchor,
                            const float* __restrict__ rel,
                            const float* __restrict__ nota,
                            const unsigned char* __restrict__ bt) {
    int bx = blockIdx.x;
    int tid = threadIdx.x;
    if (bx < NS*BB) {
        // ---- embs ----
        int n = bx & (NS-1), b = bx >> 8;
        if (tid < DD/4) {
            int st = starts[b*NS+n];
            int le = lens[b*NS+n];
            float wt = 1.0f / (float)(le + 1);
            const float4* sb4 = (const float4*)(seq + (size_t)b*LL*DD);
            float4 acc = make_float4(0.f,0.f,0.f,0.f);
            for (int w = 0; w <= le; ++w) {
                int p = st + w; if (p > LL-1) p = LL-1;
                float4 v = sb4[(size_t)p*(DD/4) + tid];
                acc.x += v.x; acc.y += v.y; acc.z += v.z; acc.w += v.w;
            }
            acc.x *= wt; acc.y *= wt; acc.z *= wt; acc.w *= wt;
            ((float4*)(g_embs + ((size_t)b*NS + n)*DD))[tid] = acc;
        }
        return;
    }
    int i = (bx - NS*BB)*256 + tid;
    if (i == 0) {
        int mode = 1;
        bool nonbin = false, oddone = false;
        for (int t = 0; t < NT; ++t) {
            unsigned char v = bt[t];
            if (v > 1) nonbin = true;
            else if (v == 1 && (t & 3) != 0) oddone = true;
        }
        if (nonbin) mode = 2;
        else if (oddone) mode = 0;
        g_btmode = mode;
    }
    // zero-fill accumulators
    if (i < ZTOT) {
        int z = i;
        if (z < ZSPS) g_sps[z] = 0.f;
        else if ((z -= ZSPS) < ZET) g_eterm[z] = 0.f;
        else if ((z -= ZET) < ZSWM) g_swm[z] = 0.f;
        else g_gg[z - ZSWM] = 0.f;
    }
    // weight transposes
    const int totA = DD*NT, totB = DD*NE, totC = DD*NC;
    if (i < totA) {
        int d = i / NT, t = i % NT;
        g_WT[i] = anchor[t*DD + d];
    } else if (i < totA + totB) {
        int i2 = i - totA;
        int d = i2 / NE, j = i2 % NE;
        float v;
        if (j < NR)            v = rel[(size_t)j*3*DD + d];
        else if (j < 2*NR)     v = rel[(size_t)(j-NR)*3*DD + DD + d];
        else if (j < 2*NR+NN)  v = nota[(size_t)(j-2*NR)*3*DD + d];
        else                   v = nota[(size_t)(j-2*NR-NN)*3*DD + DD + d];
        g_WT[i] = v;
    } else if (i < totA + totB + totC) {
        int i3 = i - totA - totB;
        int d = i3 / NC, j = i3 % NC;
        float v = (j < NR) ? rel[(size_t)j*3*DD + 2*DD + d]
                           : nota[(size_t)(j-NR)*3*DD + 2*DD + d];
        g_WT[i] = v;
    }
}

// ---------------------------------------------------------------------------
// Register-tiled GEMM with k-split + atomic epilogue
// ---------------------------------------------------------------------------
template<int MMAX>
__global__ void k_gemm(const float* __restrict__ A, long sAb,
                       const int* __restrict__ gidx, int gsb,
                       const float* __restrict__ W, long sWb,
                       float* __restrict__ C, long sCb,
                       int M, int N, int K,
                       const float* __restrict__ qsum, int qsb,
                       int ctrans) {
    constexpr int TM = 64;
    constexpr int CT = 32;
    constexpr int NPAD = MMAX*CT;
    __shared__ float As[TM*32];
    __shared__ float Ws[32*NPAD];
    int b = blockIdx.y;
    int r0 = blockIdx.x * TM;
    int tid = threadIdx.x;
    const float* Ab = A + (long)b*sAb;
    const float* Wb = W + (long)b*sWb;
    int kchunk = K / gridDim.z;
    int kbase = blockIdx.z * kchunk;

    float acc[8][MMAX];
#pragma unroll
    for (int i = 0; i < 8; ++i)
#pragma unroll
        for (int m = 0; m < MMAX; ++m) acc[i][m] = 0.f;

    int rg = tid >> 5, ct = tid & 31;

    for (int k0 = kbase; k0 < kbase + kchunk; k0 += 32) {
        for (int e = tid; e < TM*32; e += 256) {
            int r = e >> 5, c = e & 31;
            int R = r0 + r; if (R >= M) R = M-1;
            int row = gidx ? gidx[b*gsb + R] : R;
            As[e] = Ab[(long)row*K + k0 + c];
        }
        for (int e = tid; e < 32*NPAD; e += 256) {
            int r = e / NPAD, c = e % NPAD;
            Ws[e] = (c < N) ? Wb[(long)(k0+r)*N + c] : 0.f;
        }
        __syncthreads();
#pragma unroll 8
        for (int kk = 0; kk < 32; ++kk) {
            float wv[MMAX];
#pragma unroll
            for (int m = 0; m < MMAX; ++m) wv[m] = Ws[kk*NPAD + ct + m*CT];
#pragma unroll
            for (int i = 0; i < 8; ++i) {
                float av = As[(rg*8+i)*32 + kk];
#pragma unroll
                for (int m = 0; m < MMAX; ++m) acc[i][m] += av * wv[m];
            }
        }
        __syncthreads();
    }

#pragma unroll
    for (int i = 0; i < 8; ++i) {
        int R = r0 + rg*8 + i;
        if (R < M) {
            float sc = 1.f;
            if (qsum) sc = 1.f / qsum[b*qsb + R];
#pragma unroll
            for (int m = 0; m < MMAX; ++m) {
                int j = ct + m*CT;
                if (j < N) {
                    long idx = ctrans ? ((long)j*M + R) : ((long)R*N + j);
                    atomicAdd(&C[(long)b*sCb + idx], acc[i][m]*sc);
                }
            }
        }
    }
}

// ---------------------------------------------------------------------------
// Top-K: 512 threads/batch. Phase 1: split j-scan 2 ways (33 j's per thread,
// coalesced, independent loads). Phase 2: combine. Phase 3: stable rank.
// ---------------------------------------------------------------------------
__global__ void k_topk(const void* __restrict__ istrig,
                       float* __restrict__ out, int write_top) {
    __shared__ float sv[NS];
    __shared__ int   sci[NS];
    __shared__ float pm1[NS];
    __shared__ int   pi1[NS];
    int b = blockIdx.x;
    int tid = threadIdx.x;             // 0..511
    int sp = tid & (NS-1), jg = tid >> 8;
    const float* base = g_sps + (size_t)b*NS*NT;
    int j0 = jg*33;
    float mx = -INFINITY; int mi = j0;
#pragma unroll
    for (int j = 0; j < 33; ++j) {
        float v = base[(size_t)(j0+j)*NS + sp];
        if (v > mx) { mx = v; mi = j0+j; }
    }
    if (jg == 0) { sv[sp] = mx; sci[sp] = mi; }
    else         { pm1[sp] = mx; pi1[sp] = mi; }
    __syncthreads();
    if (tid < NS) {
        if (pm1[tid] > sv[tid]) { sv[tid] = pm1[tid]; sci[tid] = pi1[tid]; }
    }
    __syncthreads();
    if (tid < NS) {
        float my = sv[tid];
        int rank = 0;
#pragma unroll 8
        for (int j = 0; j < NS; ++j) {
            float vj = sv[j];
            rank += (vj > my) || (vj == my && j < tid);
        }
        if (rank < TK) {
            g_top[b*TK + rank] = tid;
            int c = sci[tid];
            int tv;
            if (g_btmode == 0)      tv = ((const unsigned char*)istrig)[c] != 0;
            else if (g_btmode == 1) tv = ((const int*)istrig)[c] != 0;
            else                    tv = ((const float*)istrig)[c] != 0.0f;
            g_trig[b*TK + rank] = tv;
            if (write_top)
                out[SZ_SCORES + SZ_PREDS + SZ_PM + b*TK + rank] = (float)tid;
        }
    }
}

// ---------------------------------------------------------------------------
// a_e: attention pooling for top-K spans only (float4; 256 threads = LL/4)
// ---------------------------------------------------------------------------
__global__ void k_ae(const float* __restrict__ att,
                     const int* __restrict__ starts,
                     const int* __restrict__ lens) {
    int h = blockIdx.x, s = blockIdx.y, b = blockIdx.z;
    int n = g_top[b*TK + s];
    int st = starts[b*NS + n], le = lens[b*NS + n];
    float wt = 1.0f / (float)(le + 1);
    const float4* ab4 = (const float4*)(att + ((size_t)(b*HH + h))*LL*LL);
    float4* ob4 = (float4*)(g_ae + (((size_t)b*TK + s)*HH + h)*LL);
    int tid = threadIdx.x;   // 0..255
    float4 acc = make_float4(0.f,0.f,0.f,0.f);
    for (int w = 0; w <= le; ++w) {
        int p = st + w; if (p > LL-1) p = LL-1;
        float4 v = ab4[(size_t)p*(LL/4) + tid];
        acc.x += v.x; acc.y += v.y; acc.z += v.z; acc.w += v.w;
    }
    acc.x *= wt; acc.y *= wt; acc.z *= wt; acc.w *= wt;
    ob4[tid] = acc;
}

// ---------------------------------------------------------------------------
// q kernel: 2D pair tiles; 4 s-slabs in 192KB smem, o streamed in chunks of 4.
// Writes unnormalized q + per-pair sums (normalization folded into gg GEMM).
// ---------------------------------------------------------------------------
#define QS 4
#define QO 16
#define QOC 4
#define NST ((TK+QS-1)/QS)   // 13
#define NOT ((TK+QO-1)/QO)   // 4

__device__ __forceinline__ int pair_idx(int s, int o) {
    return s*TK - (s*(s+1))/2 + (o - s - 1);
}

__global__ void k_q() {
    extern __shared__ float4 sA4[];     // QS*HH*LL floats = 192KB
    __shared__ float sred[QS*QOC*8];
    int b = blockIdx.y;
    int st = blockIdx.x % NST, ot = blockIdx.x / NST;
    int s0 = st*QS, o0 = ot*QO;
    {
        int o_hi = o0 + QO - 1; if (o_hi > TK-1) o_hi = TK-1;
        if (o_hi <= s0) return;
    }
    int tid = threadIdx.x;
    for (int idx = tid; idx < QS*HH*(LL/4); idx += 256) {
        int si = idx / (HH*(LL/4));
        int rem = idx % (HH*(LL/4));
        int sc = s0 + si; if (sc > TK-1) sc = TK-1;
        sA4[idx] = ((const float4*)(g_ae + ((size_t)(b*TK + sc)*HH)*LL))[rem];
    }
    __syncthreads();
    int lane = tid & 31, wid = tid >> 5;

    for (int oc = 0; oc < QO; oc += QOC) {
        int ob = o0 + oc;
        if (ob + QOC - 1 <= s0) continue;
        const float4* aeo[QOC];
#pragma unroll
        for (int oo = 0; oo < QOC; ++oo) {
            int o = ob + oo; if (o > TK-1) o = TK-1;
            aeo[oo] = (const float4*)(g_ae + ((size_t)(b*TK + o)*HH)*LL);
        }
        float4 qv[QS][QOC];
#pragma unroll
        for (int si = 0; si < QS; ++si)
#pragma unroll
            for (int oo = 0; oo < QOC; ++oo) qv[si][oo] = make_float4(0,0,0,0);

#pragma unroll
        for (int h = 0; h < HH; ++h) {
            float4 a[QS];
#pragma unroll
            for (int si = 0; si < QS; ++si) a[si] = sA4[(si*HH + h)*(LL/4) + tid];
#pragma unroll
            for (int oo = 0; oo < QOC; ++oo) {
                float4 x = aeo[oo][h*(LL/4) + tid];
#pragma unroll
                for (int si = 0; si < QS; ++si) {
                    qv[si][oo].x += a[si].x * x.x;
                    qv[si][oo].y += a[si].y * x.y;
                    qv[si][oo].z += a[si].z * x.z;
                    qv[si][oo].w += a[si].w * x.w;
                }
            }
        }
#pragma unroll
        for (int oo = 0; oo < QOC; ++oo) {
            int o = ob + oo;
#pragma unroll
            for (int si = 0; si < QS; ++si) {
                int s = s0 + si;
                float ps = 0.f;
                if (o < TK && s < o) {
                    int pr = pair_idx(s, o);
                    ((float4*)(g_q + ((size_t)b*NPAIR + pr)*LL))[tid] = qv[si][oo];
                    float4 v = qv[si][oo];
                    ps = v.x + v.y + v.z + v.w;
                }
                for (int off = 16; off; off >>= 1)
                    ps += __shfl_down_sync(0xffffffffu, ps, off);
                if (lane == 0) sred[(si*QOC + oo)*8 + wid] = ps;
            }
        }
        __syncthreads();
        if (tid < QS*QOC) {
            int si = tid / QOC, oo = tid % QOC;
            int s = s0 + si, o = ob + oo;
            if (o < TK && s < o) {
                float tot = 0.f;
#pragma unroll
                for (int w = 0; w < 8; ++w) tot += sred[tid*8 + w];
                g_qsum[(size_t)b*NPAIR + pair_idx(s, o)] = tot;
            }
        }
        __syncthreads();
    }
}

// ---------------------------------------------------------------------------
// Final scoring
// ---------------------------------------------------------------------------
__global__ void k_final(float* __restrict__ out, int write_extra) {
    __shared__ float sc[58];
    __shared__ float nv[NN];
    int o = blockIdx.x, s = blockIdx.y, b = blockIdx.z;
    int tid = threadIdx.x;
    int trig = g_trig[b*TK + s];
    int mask = (trig && (s != o)) ? 1 : 0;
    size_t so = ((size_t)b*TK + s)*TK + o;
    float* outs = out + so*58;
    if (!mask) {
        if (tid < 58) outs[tid] = 0.f;
        if (tid == 0 && write_extra) {
            out[SZ_SCORES + so] = 0.f;
            out[SZ_SCORES + SZ_PREDS + so] = 0.f;
        }
        return;
    }
    int lo = s < o ? s : o, hi = s < o ? o : s;
    int pair = lo*TK - (lo*(lo+1))/2 + (hi - lo - 1);
    const float* gg = g_gg + ((size_t)b*NPAIR + pair)*NC;
    const float* es = g_eterm + ((size_t)b*TK + s)*NE;
    const float* eo = g_eterm + ((size_t)b*TK + o)*NE;
    if (tid < NR) sc[1 + tid] = es[tid] + eo[NR + tid] + gg[tid];
    if (tid < NN) nv[tid] = es[2*NR + tid] + eo[2*NR + NN + tid] + gg[NR + tid];
    __syncthreads();
    if (tid == 0) {
        float nm = nv[0];
        for (int m = 1; m < NN; ++m) nm = fmaxf(nm, nv[m]);
        sc[0] = nm;
    }
    __syncthreads();
    if (tid < 58) outs[tid] = sc[tid];
    if (tid == 0) {
        float mx = sc[0]; int mi = 0;
        for (int c = 1; c < 58; ++c) if (sc[c] > mx) { mx = sc[c]; mi = c; }
        if (write_extra) {
            out[SZ_SCORES + so] = (float)mi;
            out[SZ_SCORES + SZ_PREDS + so] = 1.0f;
        }
    }
}

// ---------------------------------------------------------------------------
extern "C" void kernel_launch(void* const* d_in, const int* in_sizes, int n_in,
                              void* d_out, int out_size) {
    const float* seq    = (const float*)d_in[0];
    const float* att    = (const float*)d_in[1];
    const float* anchor = (const float*)d_in[2];
    const float* rel    = (const float*)d_in[3];
    const float* nota   = (const float*)d_in[4];
    const int* starts   = (const int*)d_in[5];
    const int* lens     = (const int*)d_in[6];
    const void* istrig  = d_in[7];
    float* out = (float*)d_out;

    int write_extra = (out_size >= SZ_SCORES + SZ_PREDS + SZ_PM) ? 1 : 0;
    int write_top   = (out_size >= SZ_SCORES + SZ_PREDS + SZ_PM + SZ_TOP) ? 1 : 0;

    void *p_embs, *p_top, *p_eterm, *p_swm, *p_q, *p_qsum, *p_gg, *p_wt, *p_sps;
    cudaGetSymbolAddress(&p_embs, g_embs);
    cudaGetSymbolAddress(&p_sps, g_sps);
    cudaGetSymbolAddress(&p_top, g_top);
    cudaGetSymbolAddress(&p_eterm, g_eterm);
    cudaGetSymbolAddress(&p_swm, g_swm);
    cudaGetSymbolAddress(&p_q, g_q);
    cudaGetSymbolAddress(&p_qsum, g_qsum);
    cudaGetSymbolAddress(&p_gg, g_gg);
    cudaGetSymbolAddress(&p_wt, g_WT);

    static cudaStream_t s1 = nullptr, s2 = nullptr;
    static cudaEvent_t eF = nullptr, eP = nullptr, eT = nullptr, eW = nullptr, eQ = nullptr;
    static int smem_set = 0;
    if (!s1) {
        cudaStreamCreateWithFlags(&s1, cudaStreamNonBlocking);
        cudaStreamCreateWithFlags(&s2, cudaStreamNonBlocking);
        cudaEventCreateWithFlags(&eF, cudaEventDisableTiming);
        cudaEventCreateWithFlags(&eP, cudaEventDisableTiming);
        cudaEventCreateWithFlags(&eT, cudaEventDisableTiming);
        cudaEventCreateWithFlags(&eW, cudaEventDisableTiming);
        cudaEventCreateWithFlags(&eQ, cudaEventDisableTiming);
    }
    if (!smem_set) {
        cudaFuncSetAttribute(k_q, cudaFuncAttributeMaxDynamicSharedMemorySize,
                             QS*HH*LL*(int)sizeof(float));
        smem_set = 1;
    }

    // Fork side streams
    cudaEventRecord(eF, 0);
    cudaStreamWaitEvent(s1, eF, 0);
    cudaStreamWaitEvent(s2, eF, 0);

    // main: fused prep + embs
    k_prep_embs<<<NS*BB + PREP_BLOCKS, 256>>>(seq, starts, lens,
                                              anchor, rel, nota,
                                              (const unsigned char*)istrig);
    cudaEventRecord(eP, 0);

    // s1: swm (needs only weights)
    cudaStreamWaitEvent(s1, eP, 0);
    k_gemm<3><<<dim3(16, BB, 8), 256, 0, s1>>>(
        seq, (long)LL*DD, nullptr, 0,
        (const float*)p_wt + DD*(NT+NE), 0,
        (float*)p_swm, (long)LL*NC, LL, NC, DD, nullptr, 0, 0);
    cudaEventRecord(eW, s1);

    // main: score -> topk -> eterm
    k_gemm<3><<<dim3(4, BB, 12), 256>>>(
        (const float*)p_embs, (long)NS*DD, nullptr, 0,
        (const float*)p_wt, 0,
        (float*)p_sps, (long)NS*NT, NS, NT, DD, nullptr, 0, 1 /*ctrans*/);
    k_topk<<<BB, 512>>>(istrig, out, write_top);
    cudaEventRecord(eT, 0);
    k_gemm<5><<<dim3(1, BB, 24), 256>>>(
        (const float*)p_embs, (long)NS*DD, (const int*)p_top, TK,
        (const float*)p_wt + DD*NT, 0,
        (float*)p_eterm, (long)TK*NE, TK, NE, DD, nullptr, 0, 0);

    // s2: ae -> q  (needs topk)
    cudaStreamWaitEvent(s2, eT, 0);
    k_ae<<<dim3(HH, TK, BB), 256, 0, s2>>>(att, starts, lens);
    k_q<<<dim3(NST*NOT, BB), 256, QS*HH*LL*sizeof(float), s2>>>();
    cudaEventRecord(eQ, s2);

    // main: gg (needs swm + q), then final (eterm already in-order on main)
    cudaStreamWaitEvent(0, eW, 0);
    cudaStreamWaitEvent(0, eQ, 0);
    k_gemm<3><<<dim3(20, BB, 16), 256>>>(
        (const float*)p_q, (long)NPAIR*LL, nullptr, 0,
        (const float*)p_swm, (long)LL*NC,
        (float*)p_gg, (long)NPAIR*NC, NPAIR, NC, LL,
        (const float*)p_qsum, NPAIR, 0);
    k_final<<<dim3(TK, TK, BB), 64>>>(out, write_extra);
}